// round 8
// baseline (speedup 1.0000x reference)
#include <cuda_runtime.h>
#include <math.h>

// Shapes: logits (4, 257, 131072) f32, advantages (4,) f32,
//         input_ids (4, 257) i32, labels (4, 257) i32
// Output: [loss(1) | per_token_logps(4*256) | avg_entropy_per_sample(4) | avg_entropy_truncated(4)]
//         = 1033 floats

#define THREADS 512
constexpr int BB  = 4;
constexpr int TT  = 257;
constexpr int TM1 = 256;
constexpr int VV  = 131072;
constexpr int NROWS = BB * TM1;  // 1024
// analytic correction: -sum p*log(p+eps) = H - sum p*log1p(eps/p) ~= H - V*eps
constexpr float ENT_CORR = 131072.0f * 1e-9f;

__device__ float g_H[NROWS];        // token_entropy scratch
__device__ unsigned g_done = 0;     // last-CTA counter (self-resetting)

__global__ __launch_bounds__(THREADS) void fused_kernel(
    const float* __restrict__ logits,
    const float* __restrict__ advantages,
    const int*   __restrict__ input_ids,
    const int*   __restrict__ labels,
    float*       __restrict__ out)
{
    const int row = blockIdx.x;          // 0..1023
    const int b = row >> 8;
    const int t = row & 255;
    const size_t row_off = (size_t)(b * TT + t) * VV;
    const float4* rp = reinterpret_cast<const float4*>(logits + row_off);

    const int tid  = threadIdx.x;
    const int warp = tid >> 5;
    const int lane = tid & 31;

    // Prefetch chosen logit early (thread 0 only) so the dependent LDG chain
    // overlaps the main loop instead of serializing the CTA tail.
    float xc = 0.0f;
    if (tid == 0) {
        const int chosen = input_ids[b * TT + t + 1];
        xc = logits[row_off + (size_t)chosen];
    }

    float s = 0.0f;   // sum exp(x)
    float w = 0.0f;   // sum x * exp(x)

    // V/4 = 32768 float4 per row; 2 float4 per thread per iter (high MLP).
    #pragma unroll 4
    for (int k = tid; k < VV / 8; k += THREADS) {
        float4 v0 = rp[k];
        float4 v1 = rp[k + VV / 8];
        float e0 = __expf(v0.x);
        float e1 = __expf(v0.y);
        float e2 = __expf(v0.z);
        float e3 = __expf(v0.w);
        float e4 = __expf(v1.x);
        float e5 = __expf(v1.y);
        float e6 = __expf(v1.z);
        float e7 = __expf(v1.w);
        s += ((e0 + e1) + (e2 + e3)) + ((e4 + e5) + (e6 + e7));
        w = fmaf(v0.x, e0, w);
        w = fmaf(v0.y, e1, w);
        w = fmaf(v0.z, e2, w);
        w = fmaf(v0.w, e3, w);
        w = fmaf(v1.x, e4, w);
        w = fmaf(v1.y, e5, w);
        w = fmaf(v1.z, e6, w);
        w = fmaf(v1.w, e7, w);
    }

    // warp reduction
    #pragma unroll
    for (int off = 16; off; off >>= 1) {
        s += __shfl_down_sync(0xffffffff, s, off);
        w += __shfl_down_sync(0xffffffff, w, off);
    }

    __shared__ float ss[16], sw[16];
    if (lane == 0) { ss[warp] = s; sw[warp] = w; }
    __syncthreads();

    __shared__ bool s_last;
    if (warp == 0) {
        s = (lane < 16) ? ss[lane] : 0.0f;
        w = (lane < 16) ? sw[lane] : 0.0f;
        #pragma unroll
        for (int off = 8; off; off >>= 1) {
            s += __shfl_down_sync(0xffffffff, s, off);
            w += __shfl_down_sync(0xffffffff, w, off);
        }
        if (lane == 0) {
            const float lse = logf(s);
            out[1 + row] = xc - lse;                   // per_token_logps (TEMP=1)
            g_H[row] = lse - w / s - ENT_CORR;         // token_entropy
            __threadfence();
            unsigned prev = atomicAdd(&g_done, 1u);
            s_last = (prev == (unsigned)(NROWS - 1));
        }
    }
    __syncthreads();

    if (!s_last) return;

    // ================= last CTA: finalize (512 threads, 2 halves) =========
    __shared__ float s_m[BB], s_Hm[BB], s_He[BB], s_ne[BB];
    __shared__ int s_wcnt[16];
    if (tid < BB) { s_m[tid] = 0.f; s_Hm[tid] = 0.f; s_He[tid] = 0.f; s_ne[tid] = 0.f; }
    __syncthreads();

    #pragma unroll
    for (int half = 0; half < 2; half++) {
        const int bb = (tid >> 8) + half * 2;   // 0..1 then 2..3
        const int tt = tid & 255;
        const int wid16 = tid >> 5;             // 0..15

        const int   lab   = labels[bb * TT + tt + 1];
        const float H     = g_H[bb * TM1 + tt];
        const bool  valid = (lab == 1);

        // segmented inclusive prefix of `valid` within this 256-wide batch
        const unsigned ballot = __ballot_sync(0xffffffffu, valid);
        const unsigned le_mask = (2u << lane) - 1u;
        const int lane_prefix_incl = __popc(ballot & le_mask);
        const int warp_total = __popc(ballot);

        if (lane == 0) s_wcnt[wid16] = warp_total;
        __syncthreads();

        int seg_base = 0;
        const int seg_w0 = wid16 & ~7;          // 8 warps per batch segment
        for (int j = seg_w0; j < wid16; j++) seg_base += s_wcnt[j];
        const int cum = seg_base + lane_prefix_incl;

        const bool ecm = valid && (cum >= 4) && (cum <= 100);

        float m  = valid ? 1.0f : 0.0f;
        float Hm = valid ? H : 0.0f;
        float He = ecm ? H : 0.0f;
        float ne = ecm ? 1.0f : 0.0f;
        #pragma unroll
        for (int off = 16; off; off >>= 1) {
            m  += __shfl_down_sync(0xffffffffu, m,  off);
            Hm += __shfl_down_sync(0xffffffffu, Hm, off);
            He += __shfl_down_sync(0xffffffffu, He, off);
            ne += __shfl_down_sync(0xffffffffu, ne, off);
        }
        if (lane == 0) {
            atomicAdd(&s_m[bb],  m);
            atomicAdd(&s_Hm[bb], Hm);
            atomicAdd(&s_He[bb], He);
            atomicAdd(&s_ne[bb], ne);
        }
        __syncthreads();   // also protects s_wcnt reuse across halves
    }

    if (tid < BB) {
        out[1 + NROWS + tid]      = s_Hm[tid] / s_m[tid];   // avg_entropy_per_sample
        out[1 + NROWS + BB + tid] = s_He[tid] / s_ne[tid];  // avg_entropy_truncated
    }
    if (tid == 0) {
        // ratio == 1 exactly => clipped == 1 => per_token_loss = -adv[b]
        float num = 0.f, den = 0.f;
        #pragma unroll
        for (int i = 0; i < BB; i++) {
            num += advantages[i] * s_m[i];
            den += s_m[i];
        }
        out[0] = -num / den;
        g_done = 0;   // reset for next (graph-replayed) launch
    }
}

extern "C" void kernel_launch(void* const* d_in, const int* in_sizes, int n_in,
                              void* d_out, int out_size)
{
    const float* logits     = (const float*)d_in[0];
    const float* advantages = (const float*)d_in[1];
    const int*   input_ids  = (const int*)d_in[2];
    const int*   labels     = (const int*)d_in[3];
    float* out = (float*)d_out;

    fused_kernel<<<NROWS, THREADS>>>(logits, advantages, input_ids, labels, out);
}

// round 9
// speedup vs baseline: 1.0004x; 1.0004x over previous
#include <cuda_runtime.h>
#include <math.h>

// Shapes: logits (4, 257, 131072) f32, advantages (4,) f32,
//         input_ids (4, 257) i32, labels (4, 257) i32
// Output: [loss(1) | per_token_logps(4*256) | avg_entropy_per_sample(4) | avg_entropy_truncated(4)]
//         = 1033 floats

#define THREADS 256   // 8 CTAs/SM -> 1184 slots -> single wave for grid=1024
constexpr int BB  = 4;
constexpr int TT  = 257;
constexpr int TM1 = 256;
constexpr int VV  = 131072;
constexpr int NROWS = BB * TM1;  // 1024
// analytic correction: -sum p*log(p+eps) = H - sum p*log1p(eps/p) ~= H - V*eps
constexpr float ENT_CORR = 131072.0f * 1e-9f;

__device__ float g_H[NROWS];  // token_entropy scratch

__global__ __launch_bounds__(THREADS) void row_kernel(
    const float* __restrict__ logits,
    const int*   __restrict__ input_ids,
    float*       __restrict__ out)
{
    const int row = blockIdx.x;          // 0..1023
    const int b = row >> 8;
    const int t = row & 255;
    const size_t row_off = (size_t)(b * TT + t) * VV;
    const float4* rp = reinterpret_cast<const float4*>(logits + row_off);

    const int tid  = threadIdx.x;
    const int warp = tid >> 5;
    const int lane = tid & 31;

    // Prefetch chosen logit early (thread 0 only) so its dependent LDG chain
    // overlaps the main loop.
    float xc = 0.0f;
    if (tid == 0) {
        const int chosen = input_ids[b * TT + t + 1];
        xc = __ldg(logits + row_off + (size_t)chosen);
    }

    float s = 0.0f;   // sum exp(x)
    float w = 0.0f;   // sum x * exp(x)

    // VV/4 = 32768 float4 per row; 2 float4 per thread per iter.
    // __ldcs: streaming (evict-first) — data is read exactly once.
    #pragma unroll 4
    for (int k = tid; k < VV / 8; k += THREADS) {
        float4 v0 = __ldcs(rp + k);
        float4 v1 = __ldcs(rp + k + VV / 8);
        float e0 = __expf(v0.x);
        float e1 = __expf(v0.y);
        float e2 = __expf(v0.z);
        float e3 = __expf(v0.w);
        float e4 = __expf(v1.x);
        float e5 = __expf(v1.y);
        float e6 = __expf(v1.z);
        float e7 = __expf(v1.w);
        s += ((e0 + e1) + (e2 + e3)) + ((e4 + e5) + (e6 + e7));
        w = fmaf(v0.x, e0, w);
        w = fmaf(v0.y, e1, w);
        w = fmaf(v0.z, e2, w);
        w = fmaf(v0.w, e3, w);
        w = fmaf(v1.x, e4, w);
        w = fmaf(v1.y, e5, w);
        w = fmaf(v1.z, e6, w);
        w = fmaf(v1.w, e7, w);
    }

    // warp reduction
    #pragma unroll
    for (int off = 16; off; off >>= 1) {
        s += __shfl_down_sync(0xffffffff, s, off);
        w += __shfl_down_sync(0xffffffff, w, off);
    }

    __shared__ float ss[8], sw[8];
    if (lane == 0) { ss[warp] = s; sw[warp] = w; }
    __syncthreads();

    if (warp == 0) {
        s = (lane < 8) ? ss[lane] : 0.0f;
        w = (lane < 8) ? sw[lane] : 0.0f;
        #pragma unroll
        for (int off = 4; off; off >>= 1) {
            s += __shfl_down_sync(0xffffffff, s, off);
            w += __shfl_down_sync(0xffffffff, w, off);
        }
        if (lane == 0) {
            const float lse = logf(s);
            out[1 + row] = xc - lse;                   // per_token_logps (TEMP=1)
            g_H[row] = lse - w / s - ENT_CORR;         // token_entropy
        }
    }
}

// Parallel finalize: 1024 threads, one per (b, t).
__global__ __launch_bounds__(1024) void finalize_kernel(
    const float* __restrict__ advantages,
    const int*   __restrict__ labels,
    float*       __restrict__ out)
{
    const int tid  = threadIdx.x;          // 0..1023
    const int b    = tid >> 8;             // 0..3
    const int t    = tid & 255;            // 0..255
    const int wid  = tid >> 5;             // 0..31
    const int lane = tid & 31;

    const int   lab   = labels[b * TT + t + 1];
    const float H     = g_H[tid];
    const bool  valid = (lab == 1);

    // ---- segmented prefix sum of `valid` over each 256-wide batch segment ----
    const unsigned ballot = __ballot_sync(0xffffffffu, valid);
    const unsigned le_mask = (2u << lane) - 1u;       // lanes <= lane
    const int lane_prefix_incl = __popc(ballot & le_mask);
    const int warp_total = __popc(ballot);

    __shared__ int s_wcnt[32];
    if (lane == 0) s_wcnt[wid] = warp_total;
    __syncthreads();

    int seg_base = 0;
    const int seg_w0 = wid & ~7;                      // 8 warps per batch segment
    for (int j = seg_w0; j < wid; j++) seg_base += s_wcnt[j];
    const int cum = seg_base + lane_prefix_incl;      // inclusive cumsum

    const bool ecm = valid && (cum >= 4) && (cum <= 100);

    // ---- four masked reductions per batch ----
    float m  = valid ? 1.0f : 0.0f;
    float Hm = valid ? H : 0.0f;
    float He = ecm ? H : 0.0f;
    float ne = ecm ? 1.0f : 0.0f;
    #pragma unroll
    for (int off = 16; off; off >>= 1) {
        m  += __shfl_down_sync(0xffffffffu, m,  off);
        Hm += __shfl_down_sync(0xffffffffu, Hm, off);
        He += __shfl_down_sync(0xffffffffu, He, off);
        ne += __shfl_down_sync(0xffffffffu, ne, off);
    }

    __shared__ float s_m[BB], s_Hm[BB], s_He[BB], s_ne[BB];
    if (tid < BB)      { s_m[tid] = 0.f; s_Hm[tid] = 0.f; s_He[tid] = 0.f; s_ne[tid] = 0.f; }
    __syncthreads();
    if (lane == 0) {
        atomicAdd(&s_m[b],  m);
        atomicAdd(&s_Hm[b], Hm);
        atomicAdd(&s_He[b], He);
        atomicAdd(&s_ne[b], ne);
    }
    __syncthreads();

    if (tid < BB) {
        out[1 + NROWS + tid]      = s_Hm[tid] / s_m[tid];   // avg_entropy_per_sample
        out[1 + NROWS + BB + tid] = s_He[tid] / s_ne[tid];  // avg_entropy_truncated
    }
    if (tid == 0) {
        // ratio == 1 exactly => clipped == 1 => per_token_loss = -adv[b]
        float num = 0.f, den = 0.f;
        #pragma unroll
        for (int i = 0; i < BB; i++) {
            num += advantages[i] * s_m[i];
            den += s_m[i];
        }
        out[0] = -num / den;
    }
}

extern "C" void kernel_launch(void* const* d_in, const int* in_sizes, int n_in,
                              void* d_out, int out_size)
{
    const float* logits     = (const float*)d_in[0];
    const float* advantages = (const float*)d_in[1];
    const int*   input_ids  = (const int*)d_in[2];
    const int*   labels     = (const int*)d_in[3];
    float* out = (float*)d_out;

    row_kernel<<<NROWS, THREADS>>>(logits, input_ids, out);
    finalize_kernel<<<1, 1024>>>(advantages, labels, out);
}